// round 7
// baseline (speedup 1.0000x reference)
#include <cuda_runtime.h>
#include <cuda_bf16.h>

// Problem dims
#define TSTEPS 499
#define BDIM 64
#define NDIM 512
#define DDIM 100
#define ODIM 10
#define KCAT 1536

// RNN kernel config
#define NCTA 128
#define NTHR 256
#define CHUNK 128
#define NCHUNK 12

// Padded SMEM strides (floats); all %32 == 8 or 4 -> conflict-free float4 reads
#define WM1_STRIDE 1544
#define WPMD_STRIDE 1032
#define WS1_STRIDE 520
#define RS_STRIDE 132
#define RS_BUF (BDIM * RS_STRIDE)

// ---------------- device scratch (static; no allocations) ----------------
__device__ float g_U[2][TSTEPS][BDIM][NDIM];   // [0]=pmd input drive, [1]=s1 (bias folded in)
__device__ float g_r[2][BDIM][KCAT];           // ping-pong rcat = [r_m1 | r_pmd | r_s1], [b][k]
__device__ float g_rm1h[TSTEPS][BDIM][NDIM];   // r_m1 history for deferred output GEMM
__device__ unsigned g_gen;
__device__ unsigned g_count;

// ---------------- init: reset barrier state + zero initial rates ----------------
__global__ void init_kernel() {
  int tid = blockIdx.x * blockDim.x + threadIdx.x;
  if (tid == 0) { g_gen = 0u; g_count = 0u; }
  float* r0 = &g_r[0][0][0];
  const int total = BDIM * KCAT;
  for (int i = tid; i < total; i += gridDim.x * blockDim.x) r0[i] = 0.0f;
}

// ---------------- time-parallel input projections ----------------
// U[reg][t-1][b][n] = X[t] @ W_in^T + bias   (reg 0: pmd, 1: s1)
// grid: (TSTEPS, 32): y>>4 = region, (y>>3)&1 = b-half, y&7 = 64-wide n-block
__global__ void input_proj_kernel(const float* __restrict__ X,
                                  const float* __restrict__ W_in_pmd,
                                  const float* __restrict__ W_in_s1,
                                  const float* __restrict__ b_pmd,
                                  const float* __restrict__ b_s1) {
  __shared__ __align__(16) float Xs[32][DDIM];
  __shared__ __align__(16) float Ws[64][DDIM];
  const int tIdx  = blockIdx.x;
  const int y     = blockIdx.y;
  const int reg   = y >> 4;
  const int bhalf = (y >> 3) & 1;
  const int nblk  = y & 7;
  const int b0 = bhalf * 32;
  const int n0 = nblk * 64;
  const float* W    = reg ? W_in_s1 : W_in_pmd;
  const float* bias = reg ? b_s1    : b_pmd;
  const float* Xt = X + (size_t)(tIdx + 1) * (BDIM * DDIM);
  const int tid = threadIdx.x;

  for (int i = tid; i < 32 * DDIM; i += NTHR)
    Xs[i / DDIM][i % DDIM] = Xt[(b0 + i / DDIM) * DDIM + (i % DDIM)];
  for (int i = tid; i < 64 * DDIM; i += NTHR)
    Ws[i / DDIM][i % DDIM] = W[(n0 + i / DDIM) * DDIM + (i % DDIM)];
  __syncthreads();

  const int ty = tid >> 4, tx = tid & 15;
  const int bb = 2 * ty, nn = 4 * tx;
  float acc[2][4];
#pragma unroll
  for (int j = 0; j < 4; j++) {
    float bv = bias[n0 + nn + j];
    acc[0][j] = bv; acc[1][j] = bv;
  }
#pragma unroll
  for (int k = 0; k < DDIM; k += 4) {
    float4 x0 = *(const float4*)&Xs[bb][k];
    float4 x1 = *(const float4*)&Xs[bb + 1][k];
#pragma unroll
    for (int j = 0; j < 4; j++) {
      float4 wv = *(const float4*)&Ws[nn + j][k];
      acc[0][j] += x0.x * wv.x + x0.y * wv.y + x0.z * wv.z + x0.w * wv.w;
      acc[1][j] += x1.x * wv.x + x1.y * wv.y + x1.z * wv.z + x1.w * wv.w;
    }
  }
#pragma unroll
  for (int i2 = 0; i2 < 2; i2++)
#pragma unroll
    for (int j = 0; j < 4; j++)
      g_U[reg][tIdx][b0 + bb + i2][n0 + nn + j] = acc[i2][j];
}

// ---------------- persistent serial RNN core ----------------
__device__ __forceinline__ void cp_chunk(float* dst, const float* src, int tid) {
  // copies 64 rows x 128 floats (src row stride KCAT) -> smem (row stride RS_STRIDE)
#pragma unroll
  for (int j = 0; j < 8; j++) {
    int i = tid + j * NTHR;          // 0..2047 float4 segments
    int row = i >> 5;                // 32 segments per row
    int seg = i & 31;
    unsigned s = (unsigned)__cvta_generic_to_shared(dst + row * RS_STRIDE + seg * 4);
    const float* g = src + row * KCAT + seg * 4;
    asm volatile("cp.async.cg.shared.global [%0], [%1], 16;\n" :: "r"(s), "l"(g));
  }
}

extern __shared__ float s_mem[];

__global__ void __launch_bounds__(NTHR, 1)
rnn_kernel(const float* __restrict__ W_rec_m1,
           const float* __restrict__ W_rec_pmd,
           const float* __restrict__ W_rec_s1,
           const float* __restrict__ b_m1,
           const float* __restrict__ W_pmd_m1,
           const float* __restrict__ W_s1_m1,
           const float* __restrict__ W_m1_pmd) {
  float* wm1  = s_mem;                       // [4][WM1_STRIDE]  k: rec_m1 | pmd_m1 | s1_m1
  float* wpmd = wm1 + 4 * WM1_STRIDE;        // [4][WPMD_STRIDE] k: m1_pmd | rec_pmd
  float* ws1  = wpmd + 4 * WPMD_STRIDE;      // [4][WS1_STRIDE]  k: rec_s1
  float* rsb  = ws1 + 4 * WS1_STRIDE;        // [2][BDIM][RS_STRIDE] rcat chunk double buffer

  const int cta = blockIdx.x;
  const int tid = threadIdx.x;
  const int nbase = cta * 4;

  // cache this CTA's weight slices in SMEM for the whole run
  for (int i = tid; i < 4 * NDIM; i += NTHR) {
    int slot = i >> 9;
    int k = i & 511;
    int n = nbase + slot;
    wm1[slot * WM1_STRIDE + k]          = W_rec_m1[n * NDIM + k];
    wm1[slot * WM1_STRIDE + 512 + k]    = W_pmd_m1[n * NDIM + k];
    wm1[slot * WM1_STRIDE + 1024 + k]   = W_s1_m1[n * NDIM + k];
    wpmd[slot * WPMD_STRIDE + k]        = W_m1_pmd[n * NDIM + k];
    wpmd[slot * WPMD_STRIDE + 512 + k]  = W_rec_pmd[n * NDIM + k];
    ws1[slot * WS1_STRIDE + k]          = W_rec_s1[n * NDIM + k];
  }

  const int b = tid >> 2;      // row 0..63
  const int slot = tid & 3;    // column slot within CTA
  const int col = nbase + slot;
  const float bias_m1 = b_m1[col];
  const float a = 0.1f;
  const float oma = 1.0f - a;  // match jnp (1 - a) in fp32
  float x_m1 = 0.0f, x_pmd = 0.0f, x_s1 = 0.0f;
  __syncthreads();

  for (int t = 1; t <= TSTEPS; t++) {
    const float* rprev = &g_r[(t - 1) & 1][0][0];
    const float u_pmd = __ldg(&g_U[0][t - 1][b][col]);
    const float u_s1  = __ldg(&g_U[1][t - 1][b][col]);

    cp_chunk(rsb, rprev, tid);
    asm volatile("cp.async.commit_group;\n" ::: "memory");

    float4 am = make_float4(0.f, 0.f, 0.f, 0.f);
    float4 ap = make_float4(0.f, 0.f, 0.f, 0.f);
    float4 as = make_float4(0.f, 0.f, 0.f, 0.f);

    for (int ch = 0; ch < NCHUNK; ch++) {
      if (ch + 1 < NCHUNK)
        cp_chunk(rsb + ((ch + 1) & 1) * RS_BUF, rprev + (ch + 1) * CHUNK, tid);
      asm volatile("cp.async.commit_group;\n" ::: "memory");
      asm volatile("cp.async.wait_group 1;\n" ::: "memory");
      __syncthreads();

      const float* rrow = rsb + (ch & 1) * RS_BUF + b * RS_STRIDE;
      const float* w1 = wm1 + slot * WM1_STRIDE + ch * CHUNK;
      if (ch < 8) {  // k in [0,1024): m1 + pmd active
        const float* w2 = wpmd + slot * WPMD_STRIDE + ch * CHUNK;
#pragma unroll
        for (int k = 0; k < CHUNK; k += 4) {
          float4 rv = *(const float4*)(rrow + k);
          float4 v1 = *(const float4*)(w1 + k);
          float4 v2 = *(const float4*)(w2 + k);
          am.x = fmaf(rv.x, v1.x, am.x); am.y = fmaf(rv.y, v1.y, am.y);
          am.z = fmaf(rv.z, v1.z, am.z); am.w = fmaf(rv.w, v1.w, am.w);
          ap.x = fmaf(rv.x, v2.x, ap.x); ap.y = fmaf(rv.y, v2.y, ap.y);
          ap.z = fmaf(rv.z, v2.z, ap.z); ap.w = fmaf(rv.w, v2.w, ap.w);
        }
      } else {       // k in [1024,1536): m1 + s1 active
        const float* w2 = ws1 + slot * WS1_STRIDE + (ch - 8) * CHUNK;
#pragma unroll
        for (int k = 0; k < CHUNK; k += 4) {
          float4 rv = *(const float4*)(rrow + k);
          float4 v1 = *(const float4*)(w1 + k);
          float4 v2 = *(const float4*)(w2 + k);
          am.x = fmaf(rv.x, v1.x, am.x); am.y = fmaf(rv.y, v1.y, am.y);
          am.z = fmaf(rv.z, v1.z, am.z); am.w = fmaf(rv.w, v1.w, am.w);
          as.x = fmaf(rv.x, v2.x, as.x); as.y = fmaf(rv.y, v2.y, as.y);
          as.z = fmaf(rv.z, v2.z, as.z); as.w = fmaf(rv.w, v2.w, as.w);
        }
      }
      __syncthreads();
    }

    const float acc_m1  = (am.x + am.y) + (am.z + am.w);
    const float acc_pmd = (ap.x + ap.y) + (ap.z + ap.w);
    const float acc_s1  = (as.x + as.y) + (as.z + as.w);

    x_m1  = oma * x_m1  + a * (acc_m1 + bias_m1);
    x_pmd = oma * x_pmd + a * (acc_pmd + u_pmd);
    x_s1  = oma * x_s1  + a * (acc_s1 + u_s1);
    const float r_m1  = tanhf(x_m1);
    const float r_pmd = tanhf(x_pmd);
    const float r_s1v = tanhf(x_s1);

    float* rnext = &g_r[t & 1][0][0];
    rnext[b * KCAT + col]        = r_m1;
    rnext[b * KCAT + 512 + col]  = r_pmd;
    rnext[b * KCAT + 1024 + col] = r_s1v;
    g_rm1h[t - 1][b][col] = r_m1;

    // ---- grid barrier (monotone generation; all 128 CTAs resident) ----
    __threadfence();
    __syncthreads();
    if (tid == 0) {
      unsigned prev = atomicAdd(&g_count, 1u);
      if (prev == (unsigned)NCTA * (unsigned)t - 1u) {
        __threadfence();
        *((volatile unsigned*)&g_gen) = (unsigned)t;
      } else {
        while (*((volatile unsigned*)&g_gen) < (unsigned)t) __nanosleep(64);
        __threadfence();
      }
    }
    __syncthreads();
  }
}

// ---------------- time-parallel output projection ----------------
__global__ void output_kernel(const float* __restrict__ W_out, float* __restrict__ out) {
  __shared__ __align__(16) float Ws[ODIM * NDIM];
  const int t = blockIdx.x;
  for (int i = threadIdx.x; i < ODIM * NDIM; i += blockDim.x) Ws[i] = W_out[i];
  __syncthreads();
  const float* R = &g_rm1h[t][0][0];
  for (int idx = threadIdx.x; idx < BDIM * ODIM; idx += blockDim.x) {
    int bb = idx / ODIM, o = idx % ODIM;
    const float* r = R + bb * NDIM;
    const float* w = Ws + o * NDIM;
    float s = 0.0f;
#pragma unroll 8
    for (int k = 0; k < NDIM; k += 4) {
      float4 rv = *(const float4*)(r + k);
      float4 wv = *(const float4*)(w + k);
      s += rv.x * wv.x + rv.y * wv.y + rv.z * wv.z + rv.w * wv.w;
    }
    out[t * (BDIM * ODIM) + idx] = s;
  }
}

// ---------------- launch ----------------
extern "C" void kernel_launch(void* const* d_in, const int* in_sizes, int n_in,
                              void* d_out, int out_size) {
  const float* X         = (const float*)d_in[0];
  const float* W_rec_m1  = (const float*)d_in[1];
  const float* W_rec_pmd = (const float*)d_in[2];
  const float* W_rec_s1  = (const float*)d_in[3];
  const float* b_m1      = (const float*)d_in[4];
  const float* b_pmd     = (const float*)d_in[5];
  const float* b_s1      = (const float*)d_in[6];
  const float* W_pmd_m1  = (const float*)d_in[7];
  const float* W_s1_m1   = (const float*)d_in[8];
  const float* W_m1_pmd  = (const float*)d_in[9];
  const float* W_in_pmd  = (const float*)d_in[10];
  const float* W_in_s1   = (const float*)d_in[11];
  const float* W_out     = (const float*)d_in[12];
  float* out = (float*)d_out;

  init_kernel<<<64, 256>>>();

  dim3 gA(TSTEPS, 32);
  input_proj_kernel<<<gA, NTHR>>>(X, W_in_pmd, W_in_s1, b_pmd, b_s1);

  const int smem_bytes =
      (4 * WM1_STRIDE + 4 * WPMD_STRIDE + 4 * WS1_STRIDE + 2 * RS_BUF) * (int)sizeof(float);
  cudaFuncSetAttribute(rnn_kernel, cudaFuncAttributeMaxDynamicSharedMemorySize, smem_bytes);
  rnn_kernel<<<NCTA, NTHR, smem_bytes>>>(W_rec_m1, W_rec_pmd, W_rec_s1, b_m1,
                                         W_pmd_m1, W_s1_m1, W_m1_pmd);

  output_kernel<<<TSTEPS, 256>>>(W_out, out);
}